// round 7
// baseline (speedup 1.0000x reference)
#include <cuda_runtime.h>

#define BB 32
#define NP1 2048
#define NP2 1024
#define NP3 512
#define KK1 6
#define KK2 4
#define KK3 3

// scratch (static device globals; no allocation)
__device__ float g_uv[BB * NP1 * 128];
__device__ float g_h1[BB * NP1 * 64];
__device__ int   g_idx1[BB * NP1 * KK1];
__device__ int   g_sel1[BB * NP2];
__device__ float g_pos2[BB * NP2 * 3];
__device__ float g_h1s[BB * NP2 * 64];
__device__ int   g_idx2[BB * NP2 * KK2];
__device__ float g_h2[BB * NP2 * 64];
__device__ int   g_sel2[BB * NP3];
__device__ float g_pos3[BB * NP3 * 3];
__device__ float g_h2s[BB * NP3 * 64];
__device__ int   g_idx3[BB * NP3 * KK3];
__device__ float g_h3[BB * NP3 * 64];

// ---------------- kNN: brute force, whole graph in smem ----------------
template<int NP, int K>
__global__ void __launch_bounds__(256) knn_kernel(const float* __restrict__ pos,
                                                  int* __restrict__ idx) {
    __shared__ float4 sp[NP];
    const int bpg = NP / 256;
    const int b = blockIdx.x / bpg;
    const int q0 = (blockIdx.x % bpg) * 256;
    const float* p = pos + b * NP * 3;
    for (int i = threadIdx.x; i < NP; i += 256)
        sp[i] = make_float4(p[3*i], p[3*i+1], p[3*i+2], 0.f);
    __syncthreads();
    const int q = q0 + threadIdx.x;
    const float4 pq = sp[q];
    float bd[K]; int bi[K];
#pragma unroll
    for (int t = 0; t < K; t++) { bd[t] = 3.4e38f; bi[t] = 0; }
#pragma unroll 4
    for (int j = 0; j < NP; j++) {
        float4 pj = sp[j];
        float dx = pq.x - pj.x, dy = pq.y - pj.y, dz = pq.z - pj.z;
        float dd = fmaf(dx, dx, fmaf(dy, dy, dz * dz));
        if (dd < bd[K-1]) {
            bd[K-1] = dd; bi[K-1] = j;
#pragma unroll
            for (int u = K-1; u > 0; u--) {
                if (bd[u] < bd[u-1]) {   // strict: stable on ties (matches top_k)
                    float tf = bd[u]; bd[u] = bd[u-1]; bd[u-1] = tf;
                    int   ti = bi[u]; bi[u] = bi[u-1]; bi[u-1] = ti;
                }
            }
        }
    }
#pragma unroll
    for (int t = 0; t < K; t++) idx[(b*NP + q)*K + t] = bi[t];
}

// ---------------- FPS: one block/graph, fused update+argmax, 1 bar/iter ----------------
template<int NP, int M>
__global__ void __launch_bounds__(128) fps_kernel(const float* __restrict__ pos,
                                                  int* __restrict__ sel) {
    constexpr int T = 128;
    constexpr int E = NP / T;
    __shared__ float4 sp[NP];
    __shared__ float swv[2][4];
    __shared__ int   swi[2][4];
    const int b = blockIdx.x;
    const int t = threadIdx.x;
    const float* p = pos + b * NP * 3;
    for (int i = t; i < NP; i += T)
        sp[i] = make_float4(p[3*i], p[3*i+1], p[3*i+2], 0.f);
    __syncthreads();
    float d[E], px[E], py[E], pz[E];
#pragma unroll
    for (int s = 0; s < E; s++) {
        float4 q = sp[t*E + s];
        px[s] = q.x; py[s] = q.y; pz[s] = q.z;
        d[s] = 3.4e38f;
    }
    if (t == 0) sel[b*M] = 0;
    float cx = sp[0].x, cy = sp[0].y, cz = sp[0].z;
    const int warp = t >> 5, lane = t & 31;
    for (int it = 1; it < M; it++) {
        float bv = -1.f; int bidx = t*E;
#pragma unroll
        for (int s = 0; s < E; s++) {
            float dx = px[s]-cx, dy = py[s]-cy, dz = pz[s]-cz;
            float nd = fmaf(dx, dx, fmaf(dy, dy, dz*dz));
            float dn = fminf(d[s], nd);
            d[s] = dn;
            if (dn > bv) { bv = dn; bidx = t*E + s; }  // strict >: lowest idx wins ties
        }
#pragma unroll
        for (int o = 16; o > 0; o >>= 1) {
            float ov = __shfl_down_sync(0xffffffffu, bv, o);
            int   oi = __shfl_down_sync(0xffffffffu, bidx, o);
            if (ov > bv || (ov == bv && oi < bidx)) { bv = ov; bidx = oi; }
        }
        const int par = it & 1;
        if (lane == 0) { swv[par][warp] = bv; swi[par][warp] = bidx; }
        __syncthreads();
        float fv = swv[par][0]; int fi = swi[par][0];
#pragma unroll
        for (int w = 1; w < 4; w++) {
            float wv = swv[par][w]; int wi = swi[par][w];
            if (wv > fv || (wv == fv && wi < fi)) { fv = wv; fi = wi; }
        }
        if (t == 0) sel[b*M + it] = fi;
        float4 c = sp[fi];
        cx = c.x; cy = c.y; cz = c.z;
    }
}

// ---------------- gather pos+h after FPS ----------------
template<int NPIN, int M>
__global__ void __launch_bounds__(256) gather_kernel(const float* __restrict__ pin,
                                                     const float* __restrict__ hin,
                                                     const int* __restrict__ sel,
                                                     float* __restrict__ pout,
                                                     float* __restrict__ hout) {
    int x = blockIdx.x * 256 + threadIdx.x;   // BB*M*16 float4 chunks
    if (x >= BB*M*16) return;
    int pt = x >> 4, qc = x & 15;
    int b = pt / M, m = pt - b*M;
    int s = sel[b*M + m];
    ((float4*)(hout + pt*64))[qc] = ((const float4*)(hin + (b*NPIN + s)*64))[qc];
    if (qc < 3) pout[pt*3 + qc] = pin[(b*NPIN + s)*3 + qc];
}

// ---------------- UV = H @ [Wa_top | Wa_mid] (per-node projections) ----------------
template<int CI>
__global__ void __launch_bounds__(256) uv_kernel(const float* __restrict__ H,
                                                 const float* __restrict__ Wa,
                                                 float* __restrict__ UV, int Mrows) {
    __shared__ float sB[CI * 128];
    const int tid = threadIdx.x;
    for (int x = tid; x < CI * 128; x += 256) {
        int dd = x >> 7, c = x & 127;
        sB[x] = (c < 64) ? Wa[dd*64 + c] : Wa[(CI + dd)*64 + (c - 64)];
    }
    __syncthreads();
    const int warp = tid >> 5, lane = tid & 31;
    const int c0 = lane * 4;
    for (int rr = 0; rr < 4; rr++) {
        int row = blockIdx.x * 32 + warp * 4 + rr;
        if (row >= Mrows) return;
        float h0 = 0.f, h1 = 0.f;
        if (CI == 3) { if (lane < 3) h0 = H[row*3 + lane]; }
        else { h0 = H[row*64 + lane]; h1 = H[row*64 + 32 + lane]; }
        float a0 = 0.f, a1 = 0.f, a2 = 0.f, a3 = 0.f;
#pragma unroll
        for (int dd = 0; dd < CI; dd++) {
            float hv = (dd < 32) ? __shfl_sync(0xffffffffu, h0, dd)
                                 : __shfl_sync(0xffffffffu, h1, dd - 32);
            float4 bv = *reinterpret_cast<const float4*>(&sB[dd*128 + c0]);
            a0 = fmaf(hv, bv.x, a0); a1 = fmaf(hv, bv.y, a1);
            a2 = fmaf(hv, bv.z, a2); a3 = fmaf(hv, bv.w, a3);
        }
        *reinterpret_cast<float4*>(&UV[row*128 + c0]) = make_float4(a0, a1, a2, a3);
    }
}

// ---------------- fused edge MLP ----------------
// hid = relu(U_i + V_j + rel@Wrel + ba);  out_i = relu(max_k(hid@Wb) + bb)
template<int NP, int K, int PT>
__global__ void __launch_bounds__(256) edge_kernel(
    const float* __restrict__ pos, const int* __restrict__ idx,
    const float* __restrict__ UV, const float* __restrict__ Wrel,
    const float* __restrict__ ba, const float* __restrict__ Wb,
    const float* __restrict__ bb, float* __restrict__ hout)
{
    constexpr int E  = PT * K;
    constexpr int EP = E + 8;
    extern __shared__ float sm[];
    float* sHid = sm;               // [64][EP]
    float* sOut = sm + 64 * EP;     // [64][EP]
    float* sWb  = sm + 128 * EP;    // [64][64]
    __shared__ float sWrel[192], sba[64], sbb[64];
    __shared__ int   sJ[E];
    __shared__ float sRx[E], sRy[E], sRz[E];

    const int tid = threadIdx.x;
    const int p0 = blockIdx.x * PT;
    const int b  = p0 / NP;
    const int i0 = p0 - b * NP;

    for (int x = tid; x < 4096; x += 256) sWb[x] = Wb[x];
    if (tid < 192) sWrel[tid] = Wrel[tid];
    if (tid < 64) { sba[tid] = ba[tid]; sbb[tid] = bb[tid]; }
    for (int e = tid; e < E; e += 256) {
        int pl = e / K, kk = e - pl*K;
        int il = i0 + pl;
        int j  = idx[(b*NP + il)*K + kk];
        sJ[e] = j;
        int ig = (b*NP + il)*3, jg = (b*NP + j)*3;
        sRx[e] = pos[jg]   - pos[ig];
        sRy[e] = pos[jg+1] - pos[ig+1];
        sRz[e] = pos[jg+2] - pos[ig+2];
    }
    __syncthreads();

    // phase 1: hidden, stored transposed [c][e]
    for (int x = tid; x < E*64; x += 256) {
        int c = x & 63, e = x >> 6;
        int pl = e / K;
        int ig = b*NP + i0 + pl;
        int jg = b*NP + sJ[e];
        float v = UV[ig*128 + c] + UV[jg*128 + 64 + c] + sba[c];
        v = fmaf(sRx[e], sWrel[c],       v);
        v = fmaf(sRy[e], sWrel[64 + c],  v);
        v = fmaf(sRz[e], sWrel[128 + c], v);
        sHid[c*EP + e] = fmaxf(v, 0.f);
    }
    __syncthreads();

    // phase 2: [E x 64] @ [64 x 64], 8x4 register tiles
    constexpr int NEG = E / 8;
    for (int tile = tid; tile < NEG * 16; tile += 256) {
        int eg = tile % NEG, cg = tile / NEG;
        int e0 = eg * 8, c0 = cg * 4;
        float acc[8][4];
#pragma unroll
        for (int r = 0; r < 8; r++)
#pragma unroll
            for (int cq = 0; cq < 4; cq++) acc[r][cq] = 0.f;
#pragma unroll 4
        for (int k = 0; k < 64; k++) {
            float4 ha = *(const float4*)&sHid[k*EP + e0];
            float4 hb = *(const float4*)&sHid[k*EP + e0 + 4];
            float4 w  = *(const float4*)&sWb[k*64 + c0];
            float hv[8] = {ha.x, ha.y, ha.z, ha.w, hb.x, hb.y, hb.z, hb.w};
            float wv[4] = {w.x, w.y, w.z, w.w};
#pragma unroll
            for (int r = 0; r < 8; r++)
#pragma unroll
                for (int cq = 0; cq < 4; cq++)
                    acc[r][cq] = fmaf(hv[r], wv[cq], acc[r][cq]);
        }
#pragma unroll
        for (int cq = 0; cq < 4; cq++)
#pragma unroll
            for (int r = 0; r < 8; r++)
                sOut[(c0 + cq)*EP + e0 + r] = acc[r][cq];
    }
    __syncthreads();

    // phase 3: segmented max over K + bias + relu
    for (int x = tid; x < PT*64; x += 256) {
        int c = x & 63, pl = x >> 6;
        float m = -3.4e38f;
#pragma unroll
        for (int kk = 0; kk < K; kk++) m = fmaxf(m, sOut[c*EP + pl*K + kk]);
        hout[(p0 + pl)*64 + c] = fmaxf(m + sbb[c], 0.f);
    }
}

// ---------------- head: global max-pool + [64x6] linear ----------------
__global__ void __launch_bounds__(64) head_kernel(const float* __restrict__ h3,
                                                  const float* __restrict__ Wr,
                                                  const float* __restrict__ br,
                                                  float* __restrict__ out) {
    __shared__ float g[64];
    const int b = blockIdx.x, c = threadIdx.x;
    float m = -3.4e38f;
#pragma unroll 2
    for (int p = 0; p < NP3; p++) m = fmaxf(m, h3[(b*NP3 + p)*64 + c]);
    g[c] = m;
    __syncthreads();
    if (c < 6) {
        float s = br[c];
#pragma unroll
        for (int dd = 0; dd < 64; dd++) s = fmaf(g[dd], Wr[dd*6 + c], s);
        out[b*6 + c] = s;
    }
}

extern "C" void kernel_launch(void* const* d_in, const int* in_sizes, int n_in,
                              void* d_out, int out_size) {
    const float* pos = (const float*)d_in[1];
    const float* W1a = (const float*)d_in[3];  const float* b1a = (const float*)d_in[4];
    const float* W1b = (const float*)d_in[5];  const float* b1b = (const float*)d_in[6];
    const float* W2a = (const float*)d_in[7];  const float* b2a = (const float*)d_in[8];
    const float* W2b = (const float*)d_in[9];  const float* b2b = (const float*)d_in[10];
    const float* W3a = (const float*)d_in[11]; const float* b3a = (const float*)d_in[12];
    const float* W3b = (const float*)d_in[13]; const float* b3b = (const float*)d_in[14];
    const float* Wr  = (const float*)d_in[15]; const float* br  = (const float*)d_in[16];
    float* out = (float*)d_out;

    const int smemA = (128 * (192 + 8) + 4096) * 4;   // E=192 (layers 1,3)
    const int smemB = (128 * (128 + 8) + 4096) * 4;   // E=128 (layer 2)
    cudaFuncSetAttribute(edge_kernel<NP1, KK1, 32>, cudaFuncAttributeMaxDynamicSharedMemorySize, smemA);
    cudaFuncSetAttribute(edge_kernel<NP2, KK2, 32>, cudaFuncAttributeMaxDynamicSharedMemorySize, smemB);
    cudaFuncSetAttribute(edge_kernel<NP3, KK3, 64>, cudaFuncAttributeMaxDynamicSharedMemorySize, smemA);

    float *uv, *h1, *pos2, *h1s, *h2, *pos3, *h2s, *h3;
    int *idx1, *sel1, *idx2, *sel2, *idx3;
    cudaGetSymbolAddress((void**)&uv,   g_uv);
    cudaGetSymbolAddress((void**)&h1,   g_h1);
    cudaGetSymbolAddress((void**)&idx1, g_idx1);
    cudaGetSymbolAddress((void**)&sel1, g_sel1);
    cudaGetSymbolAddress((void**)&pos2, g_pos2);
    cudaGetSymbolAddress((void**)&h1s,  g_h1s);
    cudaGetSymbolAddress((void**)&idx2, g_idx2);
    cudaGetSymbolAddress((void**)&h2,   g_h2);
    cudaGetSymbolAddress((void**)&sel2, g_sel2);
    cudaGetSymbolAddress((void**)&pos3, g_pos3);
    cudaGetSymbolAddress((void**)&h2s,  g_h2s);
    cudaGetSymbolAddress((void**)&idx3, g_idx3);
    cudaGetSymbolAddress((void**)&h3,   g_h3);

    // layer 1 (h = pos, Ci=3, k=6)
    uv_kernel<3><<<BB*NP1/32, 256>>>(pos, W1a, uv, BB*NP1);
    knn_kernel<NP1, KK1><<<BB*NP1/256, 256>>>(pos, idx1);
    edge_kernel<NP1, KK1, 32><<<BB*NP1/32, 256, smemA>>>(pos, idx1, uv, W1a + 6*64, b1a, W1b, b1b, h1);

    // FPS -> N/2 + gather
    fps_kernel<NP1, NP2><<<BB, 128>>>(pos, sel1);
    gather_kernel<NP1, NP2><<<BB*NP2*16/256, 256>>>(pos, h1, sel1, pos2, h1s);

    // layer 2 (Ci=64, k=4)
    uv_kernel<64><<<BB*NP2/32, 256>>>(h1s, W2a, uv, BB*NP2);
    knn_kernel<NP2, KK2><<<BB*NP2/256, 256>>>(pos2, idx2);
    edge_kernel<NP2, KK2, 32><<<BB*NP2/32, 256, smemB>>>(pos2, idx2, uv, W2a + 128*64, b2a, W2b, b2b, h2);

    // FPS -> N/4 + gather
    fps_kernel<NP2, NP3><<<BB, 128>>>(pos2, sel2);
    gather_kernel<NP2, NP3><<<BB*NP3*16/256, 256>>>(pos2, h2, sel2, pos3, h2s);

    // layer 3 (Ci=64, k=3)
    uv_kernel<64><<<BB*NP3/32, 256>>>(h2s, W3a, uv, BB*NP3);
    knn_kernel<NP3, KK3><<<BB*NP3/256, 256>>>(pos3, idx3);
    edge_kernel<NP3, KK3, 64><<<BB*NP3/64, 256, smemA>>>(pos3, idx3, uv, W3a + 128*64, b3a, W3b, b3b, h3);

    // head
    head_kernel<<<BB, 64>>>(h3, Wr, br, out);
}

// round 9
// speedup vs baseline: 1.3034x; 1.3034x over previous
#include <cuda_runtime.h>

#define BB 32
#define NP1 2048
#define NP2 1024
#define NP3 512
#define KK1 6
#define KK2 4
#define KK3 3

// scratch (static device globals; no allocation)
__device__ float g_uv[BB * NP1 * 128];
__device__ float g_h1[BB * NP1 * 64];
__device__ int   g_idx1[BB * NP1 * KK1];
__device__ int   g_sel1[BB * NP2];
__device__ float g_pos2[BB * NP2 * 3];
__device__ float g_h1s[BB * NP2 * 64];
__device__ int   g_idx2[BB * NP2 * KK2];
__device__ float g_h2[BB * NP2 * 64];
__device__ int   g_sel2[BB * NP3];
__device__ float g_pos3[BB * NP3 * 3];
__device__ float g_h2s[BB * NP3 * 64];
__device__ int   g_idx3[BB * NP3 * KK3];
__device__ float g_h3[BB * NP3 * 64];

// ---------------- standalone kNN (layer 3) ----------------
template<int NP, int K>
__global__ void __launch_bounds__(256) knn_kernel(const float* __restrict__ pos,
                                                  int* __restrict__ idx) {
    __shared__ float4 sp[NP];
    const int bpg = NP / 256;
    const int b = blockIdx.x / bpg;
    const int q0 = (blockIdx.x % bpg) * 256;
    const float* p = pos + b * NP * 3;
    for (int i = threadIdx.x; i < NP; i += 256)
        sp[i] = make_float4(p[3*i], p[3*i+1], p[3*i+2], 0.f);
    __syncthreads();
    const int q = q0 + threadIdx.x;
    const float4 pq = sp[q];
    float bd[K]; int bi[K];
#pragma unroll
    for (int t = 0; t < K; t++) { bd[t] = 3.4e38f; bi[t] = 0; }
#pragma unroll 4
    for (int j = 0; j < NP; j++) {
        float4 pj = sp[j];
        float dx = pq.x - pj.x, dy = pq.y - pj.y, dz = pq.z - pj.z;
        float dd = fmaf(dx, dx, fmaf(dy, dy, dz * dz));
        if (dd < bd[K-1]) {
            bd[K-1] = dd; bi[K-1] = j;
#pragma unroll
            for (int u = K-1; u > 0; u--) {
                if (bd[u] < bd[u-1]) {   // strict: stable on ties (matches top_k)
                    float tf = bd[u]; bd[u] = bd[u-1]; bd[u-1] = tf;
                    int   ti = bi[u]; bi[u] = bi[u-1]; bi[u-1] = ti;
                }
            }
        }
    }
#pragma unroll
    for (int t = 0; t < K; t++) idx[(b*NP + q)*K + t] = bi[t];
}

// ---------------- fused FPS + kNN launch ----------------
// blocks [0,BB): FPS (256 thr, redux argmax, 1 barrier/iter)
// blocks [BB, BB + BB*NP/256): kNN
template<int NP, int M, int K>
__global__ void __launch_bounds__(256) fpsknn_kernel(const float* __restrict__ pos,
                                                     int* __restrict__ sel,
                                                     int* __restrict__ idx) {
    __shared__ float4 sp[NP];
    const int t = threadIdx.x;
    if (blockIdx.x < BB) {
        // ---------------- FPS body ----------------
        constexpr int T = 256;
        constexpr int E = NP / T;
        __shared__ float swv[2][8];
        __shared__ int   swi[2][8];
        const int b = blockIdx.x;
        const float* p = pos + b * NP * 3;
        for (int i = t; i < NP; i += T)
            sp[i] = make_float4(p[3*i], p[3*i+1], p[3*i+2], 0.f);
        __syncthreads();
        float d[E], px[E], py[E], pz[E];
#pragma unroll
        for (int s = 0; s < E; s++) {
            float4 q = sp[t*E + s];
            px[s] = q.x; py[s] = q.y; pz[s] = q.z;
            d[s] = 3.4e38f;
        }
        if (t == 0) sel[b*M] = 0;
        float cx = sp[0].x, cy = sp[0].y, cz = sp[0].z;
        const int warp = t >> 5, lane = t & 31;
        for (int it = 1; it < M; it++) {
            // local max over chunk; ascending scan + strict > -> lowest local idx
            float bv = 0.f; int bidx = t*E;
#pragma unroll
            for (int s = 0; s < E; s++) {
                float dx = px[s]-cx, dy = py[s]-cy, dz = pz[s]-cz;
                float nd = fmaf(dx, dx, fmaf(dy, dy, dz*dz));
                float dn = fminf(d[s], nd);
                d[s] = dn;
                if (dn > bv) { bv = dn; bidx = t*E + s; }
            }
            // warp argmax: distances >= 0 so fp32 bits are monotone as u32
            unsigned mu = __reduce_max_sync(0xffffffffu, __float_as_uint(bv));
            unsigned mk = __ballot_sync(0xffffffffu, __float_as_uint(bv) == mu);
            int src = __ffs(mk) - 1;                 // lowest lane = lowest index
            int widx = __shfl_sync(0xffffffffu, bidx, src);
            const int par = it & 1;
            if (lane == 0) { swv[par][warp] = __uint_as_float(mu); swi[par][warp] = widx; }
            __syncthreads();
            float fv = swv[par][0]; int fi = swi[par][0];
#pragma unroll
            for (int w = 1; w < 8; w++) {            // ascending warp order; strict > keeps lowest idx
                float wv = swv[par][w];
                if (wv > fv) { fv = wv; fi = swi[par][w]; }
            }
            if (t == 0) sel[b*M + it] = fi;
            float4 c = sp[fi];
            cx = c.x; cy = c.y; cz = c.z;
        }
    } else {
        // ---------------- kNN body ----------------
        const int bpg = NP / 256;
        const int blk = blockIdx.x - BB;
        const int b = blk / bpg;
        const int q0 = (blk % bpg) * 256;
        const float* p = pos + b * NP * 3;
        for (int i = t; i < NP; i += 256)
            sp[i] = make_float4(p[3*i], p[3*i+1], p[3*i+2], 0.f);
        __syncthreads();
        const int q = q0 + t;
        const float4 pq = sp[q];
        float bd[K]; int bi[K];
#pragma unroll
        for (int u = 0; u < K; u++) { bd[u] = 3.4e38f; bi[u] = 0; }
#pragma unroll 4
        for (int j = 0; j < NP; j++) {
            float4 pj = sp[j];
            float dx = pq.x - pj.x, dy = pq.y - pj.y, dz = pq.z - pj.z;
            float dd = fmaf(dx, dx, fmaf(dy, dy, dz * dz));
            if (dd < bd[K-1]) {
                bd[K-1] = dd; bi[K-1] = j;
#pragma unroll
                for (int u = K-1; u > 0; u--) {
                    if (bd[u] < bd[u-1]) {
                        float tf = bd[u]; bd[u] = bd[u-1]; bd[u-1] = tf;
                        int   ti = bi[u]; bi[u] = bi[u-1]; bi[u-1] = ti;
                    }
                }
            }
        }
#pragma unroll
        for (int u = 0; u < K; u++) idx[(b*NP + q)*K + u] = bi[u];
    }
}

// ---------------- gather pos+h after FPS ----------------
template<int NPIN, int M>
__global__ void __launch_bounds__(256) gather_kernel(const float* __restrict__ pin,
                                                     const float* __restrict__ hin,
                                                     const int* __restrict__ sel,
                                                     float* __restrict__ pout,
                                                     float* __restrict__ hout) {
    int x = blockIdx.x * 256 + threadIdx.x;   // BB*M*16 float4 chunks
    if (x >= BB*M*16) return;
    int pt = x >> 4, qc = x & 15;
    int b = pt / M, m = pt - b*M;
    int s = sel[b*M + m];
    ((float4*)(hout + pt*64))[qc] = ((const float4*)(hin + (b*NPIN + s)*64))[qc];
    if (qc < 3) pout[pt*3 + qc] = pin[(b*NPIN + s)*3 + qc];
}

// ---------------- UV = H @ [Wa_top | Wa_mid] (per-node projections) ----------------
template<int CI>
__global__ void __launch_bounds__(256) uv_kernel(const float* __restrict__ H,
                                                 const float* __restrict__ Wa,
                                                 float* __restrict__ UV, int Mrows) {
    __shared__ float sB[CI * 128];
    const int tid = threadIdx.x;
    for (int x = tid; x < CI * 128; x += 256) {
        int dd = x >> 7, c = x & 127;
        sB[x] = (c < 64) ? Wa[dd*64 + c] : Wa[(CI + dd)*64 + (c - 64)];
    }
    __syncthreads();
    const int warp = tid >> 5, lane = tid & 31;
    const int c0 = lane * 4;
    for (int rr = 0; rr < 4; rr++) {
        int row = blockIdx.x * 32 + warp * 4 + rr;
        if (row >= Mrows) return;
        float h0 = 0.f, h1 = 0.f;
        if (CI == 3) { if (lane < 3) h0 = H[row*3 + lane]; }
        else { h0 = H[row*64 + lane]; h1 = H[row*64 + 32 + lane]; }
        float a0 = 0.f, a1 = 0.f, a2 = 0.f, a3 = 0.f;
#pragma unroll
        for (int dd = 0; dd < CI; dd++) {
            float hv = (dd < 32) ? __shfl_sync(0xffffffffu, h0, dd)
                                 : __shfl_sync(0xffffffffu, h1, dd - 32);
            float4 bv = *reinterpret_cast<const float4*>(&sB[dd*128 + c0]);
            a0 = fmaf(hv, bv.x, a0); a1 = fmaf(hv, bv.y, a1);
            a2 = fmaf(hv, bv.z, a2); a3 = fmaf(hv, bv.w, a3);
        }
        *reinterpret_cast<float4*>(&UV[row*128 + c0]) = make_float4(a0, a1, a2, a3);
    }
}

// ---------------- fused edge MLP ----------------
// hid = relu(U_i + V_j + rel@Wrel + ba);  out_i = relu(max_k(hid@Wb) + bb)
template<int NP, int K, int PT>
__global__ void __launch_bounds__(256) edge_kernel(
    const float* __restrict__ pos, const int* __restrict__ idx,
    const float* __restrict__ UV, const float* __restrict__ Wrel,
    const float* __restrict__ ba, const float* __restrict__ Wb,
    const float* __restrict__ bb, float* __restrict__ hout)
{
    constexpr int E  = PT * K;
    constexpr int EP = E + 8;
    extern __shared__ float sm[];
    float* sHid = sm;               // [64][EP]
    float* sOut = sm + 64 * EP;     // [64][EP]
    float* sWb  = sm + 128 * EP;    // [64][64]
    __shared__ float sWrel[192], sba[64], sbb[64];
    __shared__ int   sJ[E];
    __shared__ float sRx[E], sRy[E], sRz[E];

    const int tid = threadIdx.x;
    const int p0 = blockIdx.x * PT;
    const int b  = p0 / NP;
    const int i0 = p0 - b * NP;

    for (int x = tid; x < 4096; x += 256) sWb[x] = Wb[x];
    if (tid < 192) sWrel[tid] = Wrel[tid];
    if (tid < 64) { sba[tid] = ba[tid]; sbb[tid] = bb[tid]; }
    for (int e = tid; e < E; e += 256) {
        int pl = e / K, kk = e - pl*K;
        int il = i0 + pl;
        int j  = idx[(b*NP + il)*K + kk];
        sJ[e] = j;
        int ig = (b*NP + il)*3, jg = (b*NP + j)*3;
        sRx[e] = pos[jg]   - pos[ig];
        sRy[e] = pos[jg+1] - pos[ig+1];
        sRz[e] = pos[jg+2] - pos[ig+2];
    }
    __syncthreads();

    // phase 1: hidden, stored transposed [c][e]
    for (int x = tid; x < E*64; x += 256) {
        int c = x & 63, e = x >> 6;
        int pl = e / K;
        int ig = b*NP + i0 + pl;
        int jg = b*NP + sJ[e];
        float v = UV[ig*128 + c] + UV[jg*128 + 64 + c] + sba[c];
        v = fmaf(sRx[e], sWrel[c],       v);
        v = fmaf(sRy[e], sWrel[64 + c],  v);
        v = fmaf(sRz[e], sWrel[128 + c], v);
        sHid[c*EP + e] = fmaxf(v, 0.f);
    }
    __syncthreads();

    // phase 2: [E x 64] @ [64 x 64], 8x4 register tiles
    constexpr int NEG = E / 8;
    for (int tile = tid; tile < NEG * 16; tile += 256) {
        int eg = tile % NEG, cg = tile / NEG;
        int e0 = eg * 8, c0 = cg * 4;
        float acc[8][4];
#pragma unroll
        for (int r = 0; r < 8; r++)
#pragma unroll
            for (int cq = 0; cq < 4; cq++) acc[r][cq] = 0.f;
#pragma unroll 4
        for (int k = 0; k < 64; k++) {
            float4 ha = *(const float4*)&sHid[k*EP + e0];
            float4 hb = *(const float4*)&sHid[k*EP + e0 + 4];
            float4 w  = *(const float4*)&sWb[k*64 + c0];
            float hv[8] = {ha.x, ha.y, ha.z, ha.w, hb.x, hb.y, hb.z, hb.w};
            float wv[4] = {w.x, w.y, w.z, w.w};
#pragma unroll
            for (int r = 0; r < 8; r++)
#pragma unroll
                for (int cq = 0; cq < 4; cq++)
                    acc[r][cq] = fmaf(hv[r], wv[cq], acc[r][cq]);
        }
#pragma unroll
        for (int cq = 0; cq < 4; cq++)
#pragma unroll
            for (int r = 0; r < 8; r++)
                sOut[(c0 + cq)*EP + e0 + r] = acc[r][cq];
    }
    __syncthreads();

    // phase 3: segmented max over K + bias + relu
    for (int x = tid; x < PT*64; x += 256) {
        int c = x & 63, pl = x >> 6;
        float m = -3.4e38f;
#pragma unroll
        for (int kk = 0; kk < K; kk++) m = fmaxf(m, sOut[c*EP + pl*K + kk]);
        hout[(p0 + pl)*64 + c] = fmaxf(m + sbb[c], 0.f);
    }
}

// ---------------- head: global max-pool + [64x6] linear ----------------
__global__ void __launch_bounds__(64) head_kernel(const float* __restrict__ h3,
                                                  const float* __restrict__ Wr,
                                                  const float* __restrict__ br,
                                                  float* __restrict__ out) {
    __shared__ float g[64];
    const int b = blockIdx.x, c = threadIdx.x;
    float m = -3.4e38f;
#pragma unroll 2
    for (int p = 0; p < NP3; p++) m = fmaxf(m, h3[(b*NP3 + p)*64 + c]);
    g[c] = m;
    __syncthreads();
    if (c < 6) {
        float s = br[c];
#pragma unroll
        for (int dd = 0; dd < 64; dd++) s = fmaf(g[dd], Wr[dd*6 + c], s);
        out[b*6 + c] = s;
    }
}

extern "C" void kernel_launch(void* const* d_in, const int* in_sizes, int n_in,
                              void* d_out, int out_size) {
    const float* pos = (const float*)d_in[1];
    const float* W1a = (const float*)d_in[3];  const float* b1a = (const float*)d_in[4];
    const float* W1b = (const float*)d_in[5];  const float* b1b = (const float*)d_in[6];
    const float* W2a = (const float*)d_in[7];  const float* b2a = (const float*)d_in[8];
    const float* W2b = (const float*)d_in[9];  const float* b2b = (const float*)d_in[10];
    const float* W3a = (const float*)d_in[11]; const float* b3a = (const float*)d_in[12];
    const float* W3b = (const float*)d_in[13]; const float* b3b = (const float*)d_in[14];
    const float* Wr  = (const float*)d_in[15]; const float* br  = (const float*)d_in[16];
    float* out = (float*)d_out;

    const int smemA = (128 * (192 + 8) + 4096) * 4;   // E=192 (layers 1,3)
    const int smemB = (128 * (128 + 8) + 4096) * 4;   // E=128 (layer 2)
    cudaFuncSetAttribute(edge_kernel<NP1, KK1, 32>, cudaFuncAttributeMaxDynamicSharedMemorySize, smemA);
    cudaFuncSetAttribute(edge_kernel<NP2, KK2, 32>, cudaFuncAttributeMaxDynamicSharedMemorySize, smemB);
    cudaFuncSetAttribute(edge_kernel<NP3, KK3, 64>, cudaFuncAttributeMaxDynamicSharedMemorySize, smemA);

    float *uv, *h1, *pos2, *h1s, *h2, *pos3, *h2s, *h3;
    int *idx1, *sel1, *idx2, *sel2, *idx3;
    cudaGetSymbolAddress((void**)&uv,   g_uv);
    cudaGetSymbolAddress((void**)&h1,   g_h1);
    cudaGetSymbolAddress((void**)&idx1, g_idx1);
    cudaGetSymbolAddress((void**)&sel1, g_sel1);
    cudaGetSymbolAddress((void**)&pos2, g_pos2);
    cudaGetSymbolAddress((void**)&h1s,  g_h1s);
    cudaGetSymbolAddress((void**)&idx2, g_idx2);
    cudaGetSymbolAddress((void**)&h2,   g_h2);
    cudaGetSymbolAddress((void**)&sel2, g_sel2);
    cudaGetSymbolAddress((void**)&pos3, g_pos3);
    cudaGetSymbolAddress((void**)&h2s,  g_h2s);
    cudaGetSymbolAddress((void**)&idx3, g_idx3);
    cudaGetSymbolAddress((void**)&h3,   g_h3);

    // layer 1: fused fps1+knn1 (both depend only on pos), then uv1, edge1
    fpsknn_kernel<NP1, NP2, KK1><<<BB + BB*NP1/256, 256>>>(pos, sel1, idx1);
    uv_kernel<3><<<BB*NP1/32, 256>>>(pos, W1a, uv, BB*NP1);
    edge_kernel<NP1, KK1, 32><<<BB*NP1/32, 256, smemA>>>(pos, idx1, uv, W1a + 6*64, b1a, W1b, b1b, h1);

    // downsample -> N/2
    gather_kernel<NP1, NP2><<<BB*NP2*16/256, 256>>>(pos, h1, sel1, pos2, h1s);

    // layer 2: fused fps2+knn2 on pos2, then uv2, edge2
    fpsknn_kernel<NP2, NP3, KK2><<<BB + BB*NP2/256, 256>>>(pos2, sel2, idx2);
    uv_kernel<64><<<BB*NP2/32, 256>>>(h1s, W2a, uv, BB*NP2);
    edge_kernel<NP2, KK2, 32><<<BB*NP2/32, 256, smemB>>>(pos2, idx2, uv, W2a + 128*64, b2a, W2b, b2b, h2);

    // downsample -> N/4
    gather_kernel<NP2, NP3><<<BB*NP3*16/256, 256>>>(pos2, h2, sel2, pos3, h2s);

    // layer 3 (no fps): knn3, uv3, edge3
    knn_kernel<NP3, KK3><<<BB*NP3/256, 256>>>(pos3, idx3);
    uv_kernel<64><<<BB*NP3/32, 256>>>(h2s, W3a, uv, BB*NP3);
    edge_kernel<NP3, KK3, 64><<<BB*NP3/64, 256, smemA>>>(pos3, idx3, uv, W3a + 128*64, b3a, W3b, b3b, h3);

    // head
    head_kernel<<<BB, 64>>>(h3, Wr, br, out);
}